// round 6
// baseline (speedup 1.0000x reference)
#include <cuda_runtime.h>

#define NUM_RBF 64
#define CUTOFF  5.0f
#define MAX_G   64
#define BLOCK   1024
#define NCTAS   148
#define WSTRIDE 68          // 64 + 4 pad floats -> bank-group = (row+quad) mod 8

// Packed node data: {x,y,z, bits(type | batch<<5)}. No other gmem scratch needed.
__device__ __align__(16) float4 g_pos4[65536];

__global__ void __launch_bounds__(256) prep_kernel(
        const float* __restrict__ pos,
        const int*   __restrict__ types,
        const int*   __restrict__ batch,
        float*       __restrict__ out,
        int N, int G) {
    int i = blockIdx.x * blockDim.x + threadIdx.x;
    int half = (N + 1) >> 1;
    if (i < G) out[i] = 0.0f;               // d_out is poisoned; zero it here
    if (i < half) {
        int j = i + half;
        // Two nodes per thread: all loads issued before any stores (MLP=8..10).
        float x0 = __ldg(pos + 3 * i + 0);
        float y0 = __ldg(pos + 3 * i + 1);
        float z0 = __ldg(pos + 3 * i + 2);
        int   t0 = __ldg(types + i);
        int   b0 = __ldg(batch + i);
        float4 p0 = {x0, y0, z0, __int_as_float((t0 & 31) | ((b0 & 63) << 5))};
        g_pos4[i] = p0;
        if (j < N) {
            float x1 = __ldg(pos + 3 * j + 0);
            float y1 = __ldg(pos + 3 * j + 1);
            float z1 = __ldg(pos + 3 * j + 2);
            int   t1 = __ldg(types + j);
            int   b1 = __ldg(batch + j);
            float4 p1 = {x1, y1, z1, __int_as_float((t1 & 31) | ((b1 & 63) << 5))};
            g_pos4[j] = p1;
        }
    }
}

extern __shared__ float s_dyn[];

__device__ __forceinline__ void edge_compute(float4 a, float4 b, int T,
                                             const float* __restrict__ sw,
                                             float* __restrict__ esm) {
    const float DELTA     = CUTOFF / (NUM_RBF - 1);
    const float INV_DELTA = (NUM_RBF - 1) / CUTOFF;
    const float GAMMA     = (NUM_RBF / CUTOFF) * (NUM_RBF / CUTOFF);
    const float PI_OVER_C = 3.14159265358979f / CUTOFF;

    float dx = b.x - a.x, dy = b.y - a.y, dz = b.z - a.z;
    float d = sqrtf(dx * dx + dy * dy + dz * dz + 1e-12f);
    if (d < CUTOFF) {
        int ab = __float_as_int(a.w);
        int bb = __float_as_int(b.w);
        int ta = ab & 31, tb = bb & 31;
        int g  = (ab >> 5) & 63;
        int lo = min(ta, tb), hi = max(ta, tb);
        int base = (lo * T + hi) * WSTRIDE;

        float t  = d * INV_DELTA;
        int   m0 = max(0, (int)ceilf(t - 4.0f));
        int   m1 = min(NUM_RBF - 1, (int)(t + 4.0f));
        int   q0 = m0 >> 2, q1 = m1 >> 2;          // <= 3 aligned quads

        float acc = 0.0f;
        float x0  = d - (float)(q0 * 4) * DELTA;
        for (int q = q0; q <= q1; ++q) {
            float4 wv = *(const float4*)&sw[base + q * 4];
            float x1 = x0 - DELTA;
            float x2 = x1 - DELTA;
            float x3 = x2 - DELTA;
            acc = fmaf(wv.x, __expf(-GAMMA * x0 * x0), acc);
            acc = fmaf(wv.y, __expf(-GAMMA * x1 * x1), acc);
            acc = fmaf(wv.z, __expf(-GAMMA * x2 * x2), acc);
            acc = fmaf(wv.w, __expf(-GAMMA * x3 * x3), acc);
            x0 = x3 - DELTA;
        }
        float fc = 0.5f * (__cosf(PI_OVER_C * d) + 1.0f);
        atomicAdd(&esm[g], acc * fc);
    }
}

__global__ void __launch_bounds__(BLOCK, 1) edge_kernel(
        const int*   __restrict__ ei,
        const float* __restrict__ rbf,
        const float* __restrict__ filt,
        float*       __restrict__ out,
        int E, int T) {
    const int rows = T * T;
    float* sw  = s_dyn;                   // rows * WSTRIDE floats, padded
    float* esm = s_dyn + rows * WSTRIDE;  // 64 graph bins
    int tid = threadIdx.x;

    // Build fused weight table (rbf * filt) directly in smem, padded stride.
    int nq = rows * (NUM_RBF / 4);
    for (int idx = tid; idx < nq; idx += BLOCK) {
        int r = idx >> 4, q = idx & 15;
        float4 va = __ldg((const float4*)rbf + idx);
        float4 vb = __ldg((const float4*)filt + idx);
        float4 w;
        w.x = va.x * vb.x; w.y = va.y * vb.y;
        w.z = va.z * vb.z; w.w = va.w * vb.w;
        *(float4*)&sw[r * WSTRIDE + q * 4] = w;
    }
    if (tid < MAX_G) esm[tid] = 0.0f;
    __syncthreads();

    if ((E & 3) == 0) {
        int nquad = E >> 2;
        const int4* s4p = (const int4*)ei;
        const int4* d4p = (const int4*)(ei + E);
        for (int i = blockIdx.x * BLOCK + tid; i < nquad; i += NCTAS * BLOCK) {
            int4 s4 = __ldg(s4p + i);
            int4 d4 = __ldg(d4p + i);
            // Issue all 8 gathers up front for MLP.
            float4 a0 = __ldg(&g_pos4[s4.x]);
            float4 b0 = __ldg(&g_pos4[d4.x]);
            float4 a1 = __ldg(&g_pos4[s4.y]);
            float4 b1 = __ldg(&g_pos4[d4.y]);
            float4 a2 = __ldg(&g_pos4[s4.z]);
            float4 b2 = __ldg(&g_pos4[d4.z]);
            float4 a3 = __ldg(&g_pos4[s4.w]);
            float4 b3 = __ldg(&g_pos4[d4.w]);
            edge_compute(a0, b0, T, sw, esm);
            edge_compute(a1, b1, T, sw, esm);
            edge_compute(a2, b2, T, sw, esm);
            edge_compute(a3, b3, T, sw, esm);
        }
    } else {
        for (int e = blockIdx.x * BLOCK + tid; e < E; e += NCTAS * BLOCK) {
            int src = __ldg(ei + e);
            int dst = __ldg(ei + e + E);
            float4 a = __ldg(&g_pos4[src]);
            float4 b = __ldg(&g_pos4[dst]);
            edge_compute(a, b, T, sw, esm);
        }
    }

    __syncthreads();
    if (tid < MAX_G) atomicAdd(&out[tid], esm[tid]);
}

extern "C" void kernel_launch(void* const* d_in, const int* in_sizes, int n_in,
                              void* d_out, int out_size) {
    const float* pos   = (const float*)d_in[0];
    const float* rbf   = (const float*)d_in[1];
    const float* filt  = (const float*)d_in[2];
    const int*   ei    = (const int*)d_in[3];
    const int*   types = (const int*)d_in[4];
    const int*   batch = (const int*)d_in[5];

    int N  = in_sizes[0] / 3;
    int WN = in_sizes[1];
    int E  = in_sizes[3] / 2;
    int G  = out_size < MAX_G ? out_size : MAX_G;

    int T = 1;
    while (T * T * NUM_RBF < WN) T++;      // 25 for this dataset

    int smem_bytes = T * T * WSTRIDE * 4 + MAX_G * 4;
    cudaFuncSetAttribute(edge_kernel,
                         cudaFuncAttributeMaxDynamicSharedMemorySize, smem_bytes);

    int half = (N + 1) >> 1;
    int prep_blocks = (half + 255) / 256;
    prep_kernel<<<prep_blocks, 256>>>(pos, types, batch, (float*)d_out, N, G);
    edge_kernel<<<NCTAS, BLOCK, smem_bytes>>>(ei, rbf, filt, (float*)d_out, E, T);
}

// round 8
// speedup vs baseline: 1.1402x; 1.1402x over previous
#include <cuda_runtime.h>

#define NUM_RBF 64
#define CUTOFF  5.0f
#define MAX_G   64
#define BLOCK   896
#define NCTAS   148
#define WSTRIDE 68          // 64 + 4 pad floats -> bank-group = (row+quad) mod 8

// Packed node data: {x,y,z, bits(type | batch<<5)}. No other gmem scratch needed.
__device__ __align__(16) float4 g_pos4[65536];

__global__ void __launch_bounds__(256) prep_kernel(
        const float* __restrict__ pos,
        const int*   __restrict__ types,
        const int*   __restrict__ batch,
        float*       __restrict__ out,
        int N, int G) {
    int i = blockIdx.x * blockDim.x + threadIdx.x;
    if (i < G) out[i] = 0.0f;               // d_out is poisoned; zero it here
    if (i < N) {
        float4 p;
        p.x = pos[3 * i + 0];
        p.y = pos[3 * i + 1];
        p.z = pos[3 * i + 2];
        p.w = __int_as_float((types[i] & 31) | ((batch[i] & 63) << 5));
        g_pos4[i] = p;
    }
}

extern __shared__ float s_dyn[];

// Gaussian ladder constants (exact rationals evaluated in double, stored fp32):
//   DELTA = 5/63, GAMMA = (64/5)^2
//   GD2    = gamma*DELTA^2          = (64/63)^2        = 1.03199798...
//   TWOGD  = 2*gamma*DELTA          = 8192/315         = 26.0063492...
//   CMUL   = exp(-2*gamma*DELTA^2)  = exp(-2.06399597) = 0.126872539...
#define F_DELTA   0.0793650793650794f
#define F_INVD    12.6f
#define F_GAMMA   163.84f
#define F_GD2     1.0319979843990426f
#define F_TWOGD   26.006349206349206f
#define F_CMUL    0.1268725387859556f
#define F_PIOC    0.6283185307179586f

__device__ __forceinline__ void edge_compute(float4 a, float4 b, int T,
                                             const float* __restrict__ sw,
                                             float* __restrict__ esm) {
    float dx = b.x - a.x, dy = b.y - a.y, dz = b.z - a.z;
    float d = sqrtf(dx * dx + dy * dy + dz * dz + 1e-12f);
    if (d < CUTOFF) {
        int ab = __float_as_int(a.w);
        int bb = __float_as_int(b.w);
        int ta = ab & 31, tb = bb & 31;
        int g  = (ab >> 5) & 63;
        int lo = min(ta, tb), hi = max(ta, tb);
        const float* wp = sw + (lo * T + hi) * WSTRIDE;

        // Fixed 12-mu window of 3 aligned quads; mus within +-4*DELTA of d covered.
        int mc = (int)(d * F_INVD);                 // floor, d>=0
        int q0 = min(13, max(0, mc - 4) >> 2);
        wp += q0 * 4;

        // Center-seeded ladder: seed at window slot 5, where |x5| <= 6*DELTA
        // for ALL clamp cases -> e5 >= exp(-37.2), no FTZ underflow of the seed.
        // Outward terms decay geometrically; far-tail underflow (->0) is benign.
        float x5 = fmaf((float)(q0 * 4 + 5), -F_DELTA, d);
        float e5 = __expf(-F_GAMMA * x5 * x5);
        float ru = __expf(fmaf( F_TWOGD, x5, -F_GD2));  // step m -> m+1
        float rd = __expf(fmaf(-F_TWOGD, x5, -F_GD2));  // step m -> m-1

        float4 w0 = *(const float4*)(wp);       // slots 0..3
        float4 w1 = *(const float4*)(wp + 4);   // slots 4..7
        float4 w2 = *(const float4*)(wp + 8);   // slots 8..11

        float acc = w1.y * e5;                                   // k=5
        float e = e5, r = ru;                                    // upward
        e *= r; acc = fmaf(w1.z, e, acc); r *= F_CMUL;           // k=6
        e *= r; acc = fmaf(w1.w, e, acc); r *= F_CMUL;           // k=7
        e *= r; acc = fmaf(w2.x, e, acc); r *= F_CMUL;           // k=8
        e *= r; acc = fmaf(w2.y, e, acc); r *= F_CMUL;           // k=9
        e *= r; acc = fmaf(w2.z, e, acc); r *= F_CMUL;           // k=10
        e *= r; acc = fmaf(w2.w, e, acc);                        // k=11
        e = e5; r = rd;                                          // downward
        e *= r; acc = fmaf(w1.x, e, acc); r *= F_CMUL;           // k=4
        e *= r; acc = fmaf(w0.w, e, acc); r *= F_CMUL;           // k=3
        e *= r; acc = fmaf(w0.z, e, acc); r *= F_CMUL;           // k=2
        e *= r; acc = fmaf(w0.y, e, acc); r *= F_CMUL;           // k=1
        e *= r; acc = fmaf(w0.x, e, acc);                        // k=0

        float fc = 0.5f * (__cosf(F_PIOC * d) + 1.0f);
        atomicAdd(&esm[g], acc * fc);
    }
}

__global__ void __launch_bounds__(BLOCK, 1) edge_kernel(
        const int*   __restrict__ ei,
        const float* __restrict__ rbf,
        const float* __restrict__ filt,
        float*       __restrict__ out,
        int E, int T) {
    const int rows = T * T;
    float* sw  = s_dyn;                   // rows * WSTRIDE floats, padded
    float* esm = s_dyn + rows * WSTRIDE;  // 64 graph bins
    int tid = threadIdx.x;

    // Build fused weight table (rbf * filt) directly in smem, padded stride.
    int nq = rows * (NUM_RBF / 4);
    for (int idx = tid; idx < nq; idx += BLOCK) {
        int r = idx >> 4, q = idx & 15;
        float4 va = __ldg((const float4*)rbf + idx);
        float4 vb = __ldg((const float4*)filt + idx);
        float4 w;
        w.x = va.x * vb.x; w.y = va.y * vb.y;
        w.z = va.z * vb.z; w.w = va.w * vb.w;
        *(float4*)&sw[r * WSTRIDE + q * 4] = w;
    }
    if (tid < MAX_G) esm[tid] = 0.0f;
    __syncthreads();

    if ((E & 3) == 0) {
        const int nquad  = E >> 2;
        const int stride = NCTAS * BLOCK;
        const int4* s4p = (const int4*)ei;
        const int4* d4p = (const int4*)(ei + E);
        int i = blockIdx.x * BLOCK + tid;
        if (i < nquad) {
            int4 s4 = __ldg(s4p + i);
            int4 d4 = __ldg(d4p + i);
            while (true) {
                // Issue all 8 gathers up front for MLP.
                float4 a0 = __ldg(&g_pos4[s4.x]);
                float4 b0 = __ldg(&g_pos4[d4.x]);
                float4 a1 = __ldg(&g_pos4[s4.y]);
                float4 b1 = __ldg(&g_pos4[d4.y]);
                float4 a2 = __ldg(&g_pos4[s4.z]);
                float4 b2 = __ldg(&g_pos4[d4.z]);
                float4 a3 = __ldg(&g_pos4[s4.w]);
                float4 b3 = __ldg(&g_pos4[d4.w]);
                // Prefetch next iteration's indices behind the gathers.
                int inext = i + stride;
                bool more = inext < nquad;
                int4 s4n, d4n;
                if (more) { s4n = __ldg(s4p + inext); d4n = __ldg(d4p + inext); }
                edge_compute(a0, b0, T, sw, esm);
                edge_compute(a1, b1, T, sw, esm);
                edge_compute(a2, b2, T, sw, esm);
                edge_compute(a3, b3, T, sw, esm);
                if (!more) break;
                s4 = s4n; d4 = d4n; i = inext;
            }
        }
    } else {
        for (int e = blockIdx.x * BLOCK + tid; e < E; e += NCTAS * BLOCK) {
            int src = __ldg(ei + e);
            int dst = __ldg(ei + e + E);
            float4 a = __ldg(&g_pos4[src]);
            float4 b = __ldg(&g_pos4[dst]);
            edge_compute(a, b, T, sw, esm);
        }
    }

    __syncthreads();
    if (tid < MAX_G) atomicAdd(&out[tid], esm[tid]);
}

extern "C" void kernel_launch(void* const* d_in, const int* in_sizes, int n_in,
                              void* d_out, int out_size) {
    const float* pos   = (const float*)d_in[0];
    const float* rbf   = (const float*)d_in[1];
    const float* filt  = (const float*)d_in[2];
    const int*   ei    = (const int*)d_in[3];
    const int*   types = (const int*)d_in[4];
    const int*   batch = (const int*)d_in[5];

    int N  = in_sizes[0] / 3;
    int WN = in_sizes[1];
    int E  = in_sizes[3] / 2;
    int G  = out_size < MAX_G ? out_size : MAX_G;

    int T = 1;
    while (T * T * NUM_RBF < WN) T++;      // 25 for this dataset

    int smem_bytes = T * T * WSTRIDE * 4 + MAX_G * 4;
    cudaFuncSetAttribute(edge_kernel,
                         cudaFuncAttributeMaxDynamicSharedMemorySize, smem_bytes);

    int prep_blocks = (N + 255) / 256;
    prep_kernel<<<prep_blocks, 256>>>(pos, types, batch, (float*)d_out, N, G);
    edge_kernel<<<NCTAS, BLOCK, smem_bytes>>>(ei, rbf, filt, (float*)d_out, E, T);
}

// round 9
// speedup vs baseline: 1.1710x; 1.0270x over previous
#include <cuda_runtime.h>

#define NUM_RBF 64
#define CUTOFF  5.0f
#define MAX_G   64
#define BLOCK   1024
#define NCTAS   148
#define WSTRIDE 68          // 64 + 4 pad floats -> bank-group = (row+quad) mod 8

// Packed node data: {x,y,z, bits(type | batch<<5)}. No other gmem scratch needed.
__device__ __align__(16) float4 g_pos4[65536];

__global__ void __launch_bounds__(256) prep_kernel(
        const float* __restrict__ pos,
        const int*   __restrict__ types,
        const int*   __restrict__ batch,
        float*       __restrict__ out,
        int N, int G) {
    int i = blockIdx.x * blockDim.x + threadIdx.x;
    if (i < G) out[i] = 0.0f;               // d_out is poisoned; zero it here
    if (i < N) {
        float4 p;
        p.x = pos[3 * i + 0];
        p.y = pos[3 * i + 1];
        p.z = pos[3 * i + 2];
        p.w = __int_as_float((types[i] & 31) | ((batch[i] & 63) << 5));
        g_pos4[i] = p;
    }
}

extern __shared__ float s_dyn[];

// DELTA = 5/63 split into fp32 hi + residual lo (folded at compile time);
// GAMMA = (64/5)^2; TWOGD = 2*gamma*DELTA; GD2 = gamma*DELTA^2;
// CMUL = exp(-2*gamma*DELTA^2).
#define F_DH      0.0793650793650794f
#define F_DL      ((float)(5.0 / 63.0 - (double)0.0793650793650794f))
#define F_INVD    12.6f
#define F_GAMMA   163.84f
#define F_GD2     1.0319979843990426f
#define F_TWOGD   26.006349206349206f
#define F_CMUL    0.1268725387859556f
#define F_PIOC    0.6283185307179586f

__device__ __forceinline__ void edge_compute(float4 a, float4 b, int T,
                                             const float* __restrict__ sw,
                                             float* __restrict__ esm) {
    float dx = b.x - a.x, dy = b.y - a.y, dz = b.z - a.z;
    float d = sqrtf(dx * dx + dy * dy + dz * dz + 1e-12f);
    if (d < CUTOFF) {
        int ab = __float_as_int(a.w);
        int bb = __float_as_int(b.w);
        int ta = ab & 31, tb = bb & 31;
        int g  = (ab >> 5) & 63;
        int lo = min(ta, tb), hi = max(ta, tb);
        const float* wp = sw + (lo * T + hi) * WSTRIDE;

        // Fixed 12-mu window of 3 aligned quads; mus within +-4*DELTA of d covered.
        int mc = (int)(d * F_INVD);                 // floor, d>=0
        int q0 = min(13, max(0, mc - 4) >> 2);
        wp += q0 * 4;

        // Two accurate direct seeds at window slots 5 and 6 (|x| small unclamped),
        // split-DELTA offsets keep x to ~2e-8 abs error. Chains run outward from
        // the seeds, so terms near d (the only ones with e ~ 1) sit <= 2 steps
        // from a seed -> systematic ladder error ~4e-6 instead of ~3e-5.
        float i5 = (float)(q0 * 4 + 5);
        float i6 = i5 + 1.0f;
        float x5 = fmaf(i5, -F_DH, d); x5 = fmaf(i5, -F_DL, x5);
        float x6 = fmaf(i6, -F_DH, d); x6 = fmaf(i6, -F_DL, x6);
        float e5 = __expf(-F_GAMMA * x5 * x5);
        float e6 = __expf(-F_GAMMA * x6 * x6);
        float ru = __expf(fmaf( F_TWOGD, x6, -F_GD2));  // step k -> k+1 from slot 6
        float rd = __expf(fmaf(-F_TWOGD, x5, -F_GD2));  // step k -> k-1 from slot 5

        float4 w0 = *(const float4*)(wp);       // slots 0..3
        float4 w1 = *(const float4*)(wp + 4);   // slots 4..7
        float4 w2 = *(const float4*)(wp + 8);   // slots 8..11

        float acc = fmaf(w1.z, e6, w1.y * e5);                   // k=5,6
        float e = e6, r = ru;                                    // upward from 6
        e *= r; acc = fmaf(w1.w, e, acc); r *= F_CMUL;           // k=7
        e *= r; acc = fmaf(w2.x, e, acc); r *= F_CMUL;           // k=8
        e *= r; acc = fmaf(w2.y, e, acc); r *= F_CMUL;           // k=9
        e *= r; acc = fmaf(w2.z, e, acc); r *= F_CMUL;           // k=10
        e *= r; acc = fmaf(w2.w, e, acc);                        // k=11
        e = e5; r = rd;                                          // downward from 5
        e *= r; acc = fmaf(w1.x, e, acc); r *= F_CMUL;           // k=4
        e *= r; acc = fmaf(w0.w, e, acc); r *= F_CMUL;           // k=3
        e *= r; acc = fmaf(w0.z, e, acc); r *= F_CMUL;           // k=2
        e *= r; acc = fmaf(w0.y, e, acc); r *= F_CMUL;           // k=1
        e *= r; acc = fmaf(w0.x, e, acc);                        // k=0

        float fc = 0.5f * (__cosf(F_PIOC * d) + 1.0f);
        atomicAdd(&esm[g], acc * fc);
    }
}

__global__ void __launch_bounds__(BLOCK, 1) edge_kernel(
        const int*   __restrict__ ei,
        const float* __restrict__ rbf,
        const float* __restrict__ filt,
        float*       __restrict__ out,
        int E, int T) {
    const int rows = T * T;
    float* sw  = s_dyn;                   // rows * WSTRIDE floats, padded
    float* esm = s_dyn + rows * WSTRIDE;  // 64 graph bins
    int tid = threadIdx.x;

    // Build fused weight table (rbf * filt) directly in smem, padded stride.
    int nq = rows * (NUM_RBF / 4);
    for (int idx = tid; idx < nq; idx += BLOCK) {
        int r = idx >> 4, q = idx & 15;
        float4 va = __ldg((const float4*)rbf + idx);
        float4 vb = __ldg((const float4*)filt + idx);
        float4 w;
        w.x = va.x * vb.x; w.y = va.y * vb.y;
        w.z = va.z * vb.z; w.w = va.w * vb.w;
        *(float4*)&sw[r * WSTRIDE + q * 4] = w;
    }
    if (tid < MAX_G) esm[tid] = 0.0f;
    __syncthreads();

    if ((E & 3) == 0) {
        const int nquad  = E >> 2;
        const int stride = NCTAS * BLOCK;
        const int4* s4p = (const int4*)ei;
        const int4* d4p = (const int4*)(ei + E);
        int i = blockIdx.x * BLOCK + tid;
        if (i < nquad) {
            int4 s4 = __ldg(s4p + i);
            int4 d4 = __ldg(d4p + i);
            while (true) {
                // Issue all 8 gathers up front for MLP.
                float4 a0 = __ldg(&g_pos4[s4.x]);
                float4 b0 = __ldg(&g_pos4[d4.x]);
                float4 a1 = __ldg(&g_pos4[s4.y]);
                float4 b1 = __ldg(&g_pos4[d4.y]);
                float4 a2 = __ldg(&g_pos4[s4.z]);
                float4 b2 = __ldg(&g_pos4[d4.z]);
                float4 a3 = __ldg(&g_pos4[s4.w]);
                float4 b3 = __ldg(&g_pos4[d4.w]);
                // Prefetch next iteration's indices behind the gathers.
                int inext = i + stride;
                bool more = inext < nquad;
                int4 s4n, d4n;
                if (more) { s4n = __ldg(s4p + inext); d4n = __ldg(d4p + inext); }
                edge_compute(a0, b0, T, sw, esm);
                edge_compute(a1, b1, T, sw, esm);
                edge_compute(a2, b2, T, sw, esm);
                edge_compute(a3, b3, T, sw, esm);
                if (!more) break;
                s4 = s4n; d4 = d4n; i = inext;
            }
        }
    } else {
        for (int e = blockIdx.x * BLOCK + tid; e < E; e += NCTAS * BLOCK) {
            int src = __ldg(ei + e);
            int dst = __ldg(ei + e + E);
            float4 a = __ldg(&g_pos4[src]);
            float4 b = __ldg(&g_pos4[dst]);
            edge_compute(a, b, T, sw, esm);
        }
    }

    __syncthreads();
    if (tid < MAX_G) atomicAdd(&out[tid], esm[tid]);
}

extern "C" void kernel_launch(void* const* d_in, const int* in_sizes, int n_in,
                              void* d_out, int out_size) {
    const float* pos   = (const float*)d_in[0];
    const float* rbf   = (const float*)d_in[1];
    const float* filt  = (const float*)d_in[2];
    const int*   ei    = (const int*)d_in[3];
    const int*   types = (const int*)d_in[4];
    const int*   batch = (const int*)d_in[5];

    int N  = in_sizes[0] / 3;
    int WN = in_sizes[1];
    int E  = in_sizes[3] / 2;
    int G  = out_size < MAX_G ? out_size : MAX_G;

    int T = 1;
    while (T * T * NUM_RBF < WN) T++;      // 25 for this dataset

    int smem_bytes = T * T * WSTRIDE * 4 + MAX_G * 4;
    cudaFuncSetAttribute(edge_kernel,
                         cudaFuncAttributeMaxDynamicSharedMemorySize, smem_bytes);

    int prep_blocks = (N + 255) / 256;
    prep_kernel<<<prep_blocks, 256>>>(pos, types, batch, (float*)d_out, N, G);
    edge_kernel<<<NCTAS, BLOCK, smem_bytes>>>(ei, rbf, filt, (float*)d_out, E, T);
}